// round 1
// baseline (speedup 1.0000x reference)
#include <cuda_runtime.h>

#define N_GL    256
#define LTAU    1000
#define BATCH   16
#define NPOLES  16
#define NIWN    256

__device__ float g_phi[N_GL];
__device__ float g_w[N_GL];

// ---------------------------------------------------------------------------
// Gauss-Legendre nodes/weights (n=256) via Newton on the Legendre recurrence.
// 3 fp32 passes (cheap, 4-cyc fma chain) + 1 fp64 pass (edge nodes need
// double-precision z because tan(pi/2*x) amplifies node error ~9000x at the
// edges). Weight uses ODE-based derivative correction so the last pass's P'
// (evaluated at pre-update z) is corrected to the final z.
// Thread t (0..127) owns positive root #t (largest first).
// ---------------------------------------------------------------------------
__global__ void init_gl_kernel() {
    __shared__ double invd[N_GL + 1];
    __shared__ float  invf[N_GL + 1];
    const int t = threadIdx.x;
    for (int j = t; j <= N_GL; j += 128) {
        double v = (j == 0) ? 0.0 : 1.0 / (double)j;
        invd[j] = v;
        invf[j] = (float)v;
    }
    __syncthreads();

    const double PI = 3.14159265358979323846;
    const int n = N_GL;
    double zd = cos(PI * ((double)t + 0.75) / ((double)n + 0.5));
    float z = (float)zd;

    // 3 fp32 Newton passes
    for (int pass = 0; pass < 3; ++pass) {
        float p1 = 1.0f, p2 = 0.0f;
#pragma unroll 8
        for (int j = 1; j <= n; ++j) {
            float inv = invf[j];
            float p3 = p2;
            p2 = p1;
            p1 = fmaf((2.0f - inv) * z, p2, -(1.0f - inv) * p3);
        }
        float pp = (float)n * (z * p1 - p2) / (z * z - 1.0f);
        z -= p1 / pp;
    }

    // final fp64 pass: one Newton update + ODE-corrected derivative for weight
    zd = (double)z;
    double p1 = 1.0, p2 = 0.0;
#pragma unroll 4
    for (int j = 1; j <= n; ++j) {
        double inv = invd[j];
        double p3 = p2;
        p2 = p1;
        p1 = fma((2.0 - inv) * zd, p2, -(1.0 - inv) * p3);
    }
    double pp  = (double)n * (zd * p1 - p2) / (zd * zd - 1.0);
    double dz  = -p1 / pp;
    double zf  = zd + dz;
    // P'' = (2xP' - n(n+1)P) / (1-x^2)  (Legendre ODE), correct P' to zf
    double ppp = (2.0 * zd * pp - (double)n * (double)(n + 1) * p1) / (1.0 - zd * zd);
    double ppf = pp + dz * ppp;
    double wgt = 2.0 / ((1.0 - zf * zf) * ppf * ppf);
    double ph  = tan(0.5 * PI * zf);

    // nodes ascending: index t -> -zf, index (n-1-t) -> +zf
    g_phi[n - 1 - t] = (float)ph;
    g_phi[t]         = (float)(-ph);
    g_w[n - 1 - t]   = (float)wgt;
    g_w[t]           = (float)wgt;
}

// ---------------------------------------------------------------------------
// Quadrature: one block per (l, b); thread t owns node t; inner loop over
// 16 poles; block-reduce over the 256 nodes.
// ---------------------------------------------------------------------------
__global__ void __launch_bounds__(256) gtau_kernel(
    const float* __restrict__ poles_re,
    const float* __restrict__ poles_im,
    const float* __restrict__ res_re,
    const float* __restrict__ res_im,
    float* __restrict__ out)
{
    __shared__ float s_eps[NPOLES], s_gam[NPOLES], s_a[NPOLES], s_b[NPOLES];
    __shared__ float s_red[8];
    const int t = threadIdx.x;
    const int l = blockIdx.x;
    const int b = blockIdx.y;

    if (t < NPOLES) {
        s_eps[t] =  poles_re[b * NPOLES + t];
        s_gam[t] = -poles_im[b * NPOLES + t];
        s_a[t]   =  res_re[b * NPOLES + t];
        s_b[t]   =  res_im[b * NPOLES + t];
    }
    __syncthreads();

    const float tau  = (float)((double)l * 0.01);
    const float taum = tau - 10.0f;
    const float ph   = g_phi[t];

    float acc = 0.0f;
#pragma unroll
    for (int p = 0; p < NPOLES; ++p) {
        float om = fmaf(s_gam[p], ph, s_eps[p]);
        float nu = fmaf(-s_b[p], ph, s_a[p]);      // (a - b*phi); 0.5 folded below
        float a1 = fminf(fmaxf(tau  * om, -50.0f), 50.0f);
        float a2 = fminf(fmaxf(taum * om, -50.0f), 50.0f);
        float den = __expf(a1) + __expf(a2);
        acc += __fdividef(nu, den);
    }
    acc *= 0.5f * g_w[t];

    // block reduction (256 -> 1)
#pragma unroll
    for (int off = 16; off > 0; off >>= 1)
        acc += __shfl_xor_sync(0xffffffffu, acc, off);
    if ((t & 31) == 0) s_red[t >> 5] = acc;
    __syncthreads();
    if (t < 8) {
        float v = s_red[t];
#pragma unroll
        for (int off = 4; off > 0; off >>= 1)
            v += __shfl_xor_sync(0xffu, v, off);
        if (t == 0) out[b * LTAU + l] = v;
    }
}

// ---------------------------------------------------------------------------
// G0 (tau=0): Matsubara sum + asymptotic tail corrections, real part only.
// Re(c1)/iwn is purely imaginary -> no real contribution. Powers of 1/(i wn)
// reduce to signed real 1/wn^k terms. One block per batch, thread t = freq.
// ---------------------------------------------------------------------------
__global__ void __launch_bounds__(256) g0_kernel(
    const float* __restrict__ poles_re,
    const float* __restrict__ poles_im,
    const float* __restrict__ res_re,
    const float* __restrict__ res_im,
    float* __restrict__ out)
{
    __shared__ float s_red[8];
    const int b = blockIdx.x;
    const int t = threadIdx.x;

    float eps[NPOLES], gam[NPOLES], av[NPOLES], bv[NPOLES];
    float SRc1 = 0.0f, SRc2 = 0.0f, SIc3 = 0.0f, SRc4 = 0.0f, SIc5 = 0.0f;
#pragma unroll
    for (int p = 0; p < NPOLES; ++p) {
        float e =  poles_re[b * NPOLES + p];
        float g = -poles_im[b * NPOLES + p];
        float a =  res_re[b * NPOLES + p];
        float bb = res_im[b * NPOLES + p];
        eps[p] = e; gam[p] = g; av[p] = a; bv[p] = bb;
        // c1 = -(a+ib); multiply chain by z = eps - i*gam:
        // (x+iy)*(e - i g): re = x*e + y*g ; im = y*e - x*g
        float cr = -a, ci = -bb;
        float r2 = cr * e + ci * g, i2 = ci * e - cr * g;
        float r3 = r2 * e + i2 * g, i3 = i2 * e - r2 * g;
        float r4 = r3 * e + i3 * g, i4 = i3 * e - r3 * g;
        float r5 = r4 * e + i4 * g, i5 = i4 * e - r4 * g;
        (void)r5;
        SRc1 += cr; SRc2 += r2; SIc3 += i3; SRc4 += r4; SIc5 += i5;
    }

    const double PI = 3.14159265358979323846;
    const float wn = (float)((2.0 * (double)t + 1.0) * (PI / 10.0));

    float reS = 0.0f;
#pragma unroll
    for (int p = 0; p < NPOLES; ++p) {
        float d = gam[p] + wn;
        reS += (av[p] * eps[p] - bv[p] * d) / (eps[p] * eps[p] + d * d);
    }
    float iw  = 1.0f / wn;
    float iw2 = iw * iw;
    // Re(G_iwn(w)) = reS + SRc2/wn^2 + SIc3/wn^3 - SRc4/wn^4 - SIc5/wn^5
    float reG = reS + iw2 * (SRc2 + SIc3 * iw - SRc4 * iw2 - SIc5 * iw2 * iw);

    float acc = reG;
#pragma unroll
    for (int off = 16; off > 0; off >>= 1)
        acc += __shfl_xor_sync(0xffffffffu, acc, off);
    if ((t & 31) == 0) s_red[t >> 5] = acc;
    __syncthreads();
    if (t < 8) {
        float v = s_red[t];
#pragma unroll
        for (int off = 4; off > 0; off >>= 1)
            v += __shfl_xor_sync(0xffu, v, off);
        if (t == 0) {
            const float C0 = -0.5f;
            const float C1 = -2.5f;                                      // -BETA/4
            const float C2 = (float)(-7.0 * 1.2020569031595942 * 100.0 /
                                     (4.0 * PI * PI * PI));
            const float C3 = (float)(1000.0 / 48.0);
            const float C4 = (float)(31.0 * 1.0369277551433699 * 10000.0 /
                                     (16.0 * PI * PI * PI * PI * PI));
            float G0 = C0 * SRc1 + C1 * SRc2 + C2 * SIc3 + C3 * SRc4 + C4 * SIc5
                     + 0.2f * v;                                         // 2/BETA
            out[b * LTAU + 0] = G0;
        }
    }
}

extern "C" void kernel_launch(void* const* d_in, const int* in_sizes, int n_in,
                              void* d_out, int out_size) {
    (void)in_sizes; (void)n_in; (void)out_size;
    const float* pre = (const float*)d_in[0];
    const float* pim = (const float*)d_in[1];
    const float* rre = (const float*)d_in[2];
    const float* rim = (const float*)d_in[3];
    float* out = (float*)d_out;

    init_gl_kernel<<<1, 128>>>();
    dim3 grid(LTAU, BATCH);
    gtau_kernel<<<grid, 256>>>(pre, pim, rre, rim, out);
    g0_kernel<<<BATCH, 256>>>(pre, pim, rre, rim, out);
}

// round 2
// speedup vs baseline: 2.7555x; 2.7555x over previous
#include <cuda_runtime.h>

#define N_GL    256
#define LTAU    1000
#define BATCH   16
#define NPOLES  16

__device__ float g_phi[N_GL];
__device__ float g_w[N_GL];

// ---------------------------------------------------------------------------
// Gauss-Legendre nodes/weights, fp32 only. Edge-node phi precision doesn't
// matter (those quadrature terms are e^{-tau*omega} ~ 0 for all tau >= dtau,
// and tau=0 is computed analytically in g0).
// ---------------------------------------------------------------------------
__global__ void init_gl_kernel() {
    __shared__ float cA[N_GL + 1], cB[N_GL + 1];
    const int t = threadIdx.x;
    for (int j = t; j <= N_GL; j += 128) {
        float inv = (j == 0) ? 0.0f : 1.0f / (float)j;
        cA[j] = 2.0f - inv;
        cB[j] = 1.0f - inv;
    }
    __syncthreads();

    const float PI = 3.14159265358979323846f;
    float z = cosf(PI * ((float)t + 0.75f) / ((float)N_GL + 0.5f));

    float pp = 1.0f;
    for (int pass = 0; pass < 4; ++pass) {
        float p1 = 1.0f, p2 = 0.0f;
#pragma unroll 8
        for (int j = 1; j <= N_GL; ++j) {
            float p3 = p2;
            p2 = p1;
            p1 = fmaf(cA[j] * z, p2, -cB[j] * p3);
        }
        pp = (float)N_GL * (z * p1 - p2) / (z * z - 1.0f);
        z -= p1 / pp;
    }

    float wgt = 2.0f / ((1.0f - z * z) * pp * pp);
    float ph  = tanf(0.5f * PI * z);

    g_phi[N_GL - 1 - t] = ph;
    g_phi[t]            = -ph;
    g_w[N_GL - 1 - t]   = wgt;
    g_w[t]              = wgt;
}

__global__ void zero_out_kernel(float* __restrict__ out) {
    int i = blockIdx.x * 256 + threadIdx.x;
    if (i < BATCH * LTAU) out[i] = 0.0f;
}

// ---------------------------------------------------------------------------
// Quadrature via geometric recurrence.
//   term(l) = C * exp(-tau_eff(l)*s),  s = |omega|,
//   C = 0.5*(a-b*phi)*w / (1+exp(-10*s))
//   omega>0: tau_eff = tau_l        (contribution decays with l ascending)
//   omega<0: tau_eff = 10 - tau_l   (decays with l descending -> write 999-l)
// Lane lam owns l = 32c+lam (fwd) / 999-(32c+lam) (bwd). Per chunk each state
// costs 2 fma + 1 mul; E advances by m32 = exp(-0.32*s) per chunk. Both
// directions strictly decay: no overflow, underflow->0 is exact enough.
// Warp = one node x 16 poles. Block = 8 warps (8 nodes). 512 blocks.
// ---------------------------------------------------------------------------
__global__ void __launch_bounds__(256) gtau_kernel(
    const float* __restrict__ poles_re,
    const float* __restrict__ poles_im,
    const float* __restrict__ res_re,
    const float* __restrict__ res_im,
    float* __restrict__ out)
{
    __shared__ float sF[2][8][32];
    __shared__ float sB[2][8][32];

    const int t    = threadIdx.x;
    const int lane = t & 31;
    const int wid  = t >> 5;
    const int B    = blockIdx.x;          // 0..511
    const int b    = B >> 5;              // batch
    const int node = ((B & 31) << 3) + wid;

    const float phi = g_phi[node];
    const float w   = g_w[node];

    float E[NPOLES], CF[NPOLES], CB[NPOLES], M[NPOLES];
#pragma unroll
    for (int p = 0; p < NPOLES; ++p) {
        float eps =  poles_re[b * NPOLES + p];
        float gam = -poles_im[b * NPOLES + p];
        float a   =  res_re[b * NPOLES + p];
        float bb  =  res_im[b * NPOLES + p];

        float om = fmaf(gam, phi, eps);
        float s  = fabsf(om);
        float numer = 0.5f * w * fmaf(-bb, phi, a);
        float C = numer / (1.0f + __expf(-10.0f * s));
        bool fwd = (om >= 0.0f);
        CF[p] = fwd ? C : 0.0f;
        CB[p] = fwd ? 0.0f : C;
        M[p]  = __expf(-0.32f * s);
        // E at chunk 0: fwd exponent -0.01*lane*s ; bwd -0.01*(lane+1)*s
        float k = fwd ? (float)lane : (float)(lane + 1);
        E[p] = __expf(-0.01f * k * s);
    }

    float* outb = out + b * LTAU;

    for (int c = 0; c < 32; ++c) {
        float aF = 0.0f, aB = 0.0f;
#pragma unroll
        for (int p = 0; p < NPOLES; ++p) {
            aF = fmaf(CF[p], E[p], aF);
            aB = fmaf(CB[p], E[p], aB);
            E[p] *= M[p];
        }
        const int buf = c & 1;
        sF[buf][wid][lane] = aF;
        sB[buf][wid][lane] = aB;
        __syncthreads();
        if (wid == 0) {
            float v = sF[buf][0][lane] + sF[buf][1][lane] + sF[buf][2][lane]
                    + sF[buf][3][lane] + sF[buf][4][lane] + sF[buf][5][lane]
                    + sF[buf][6][lane] + sF[buf][7][lane];
            int l = c * 32 + lane;
            if (l < LTAU) atomicAdd(outb + l, v);
        } else if (wid == 1) {
            float v = sB[buf][0][lane] + sB[buf][1][lane] + sB[buf][2][lane]
                    + sB[buf][3][lane] + sB[buf][4][lane] + sB[buf][5][lane]
                    + sB[buf][6][lane] + sB[buf][7][lane];
            int l = (LTAU - 1) - (c * 32 + lane);
            if (l >= 0) atomicAdd(outb + l, v);
        }
    }
}

// ---------------------------------------------------------------------------
// G0 (tau=0): Matsubara sum + asymptotic tail corrections, real part only.
// ---------------------------------------------------------------------------
__global__ void __launch_bounds__(256) g0_kernel(
    const float* __restrict__ poles_re,
    const float* __restrict__ poles_im,
    const float* __restrict__ res_re,
    const float* __restrict__ res_im,
    float* __restrict__ out)
{
    __shared__ float s_red[8];
    const int b = blockIdx.x;
    const int t = threadIdx.x;

    float eps[NPOLES], gam[NPOLES], av[NPOLES], bv[NPOLES];
    float SRc1 = 0.0f, SRc2 = 0.0f, SIc3 = 0.0f, SRc4 = 0.0f, SIc5 = 0.0f;
#pragma unroll
    for (int p = 0; p < NPOLES; ++p) {
        float e =  poles_re[b * NPOLES + p];
        float g = -poles_im[b * NPOLES + p];
        float a =  res_re[b * NPOLES + p];
        float bb = res_im[b * NPOLES + p];
        eps[p] = e; gam[p] = g; av[p] = a; bv[p] = bb;
        float cr = -a, ci = -bb;
        float r2 = cr * e + ci * g, i2 = ci * e - cr * g;
        float r3 = r2 * e + i2 * g, i3 = i2 * e - r2 * g;
        float r4 = r3 * e + i3 * g, i4 = i3 * e - r3 * g;
        float i5 = i4 * e - r4 * g;
        SRc1 += cr; SRc2 += r2; SIc3 += i3; SRc4 += r4; SIc5 += i5;
    }

    const double PI = 3.14159265358979323846;
    const float wn = (float)((2.0 * (double)t + 1.0) * (PI / 10.0));

    float reS = 0.0f;
#pragma unroll
    for (int p = 0; p < NPOLES; ++p) {
        float d = gam[p] + wn;
        reS += (av[p] * eps[p] - bv[p] * d) / (eps[p] * eps[p] + d * d);
    }
    float iw  = 1.0f / wn;
    float iw2 = iw * iw;
    float reG = reS + iw2 * (SRc2 + SIc3 * iw - SRc4 * iw2 - SIc5 * iw2 * iw);

    float acc = reG;
#pragma unroll
    for (int off = 16; off > 0; off >>= 1)
        acc += __shfl_xor_sync(0xffffffffu, acc, off);
    if ((t & 31) == 0) s_red[t >> 5] = acc;
    __syncthreads();
    if (t < 8) {
        float v = s_red[t];
#pragma unroll
        for (int off = 4; off > 0; off >>= 1)
            v += __shfl_xor_sync(0xffu, v, off);
        if (t == 0) {
            const float C0 = -0.5f;
            const float C1 = -2.5f;
            const float C2 = (float)(-7.0 * 1.2020569031595942 * 100.0 /
                                     (4.0 * PI * PI * PI));
            const float C3 = (float)(1000.0 / 48.0);
            const float C4 = (float)(31.0 * 1.0369277551433699 * 10000.0 /
                                     (16.0 * PI * PI * PI * PI * PI));
            float G0 = C0 * SRc1 + C1 * SRc2 + C2 * SIc3 + C3 * SRc4 + C4 * SIc5
                     + 0.2f * v;
            out[b * LTAU + 0] = G0;
        }
    }
}

extern "C" void kernel_launch(void* const* d_in, const int* in_sizes, int n_in,
                              void* d_out, int out_size) {
    (void)in_sizes; (void)n_in; (void)out_size;
    const float* pre = (const float*)d_in[0];
    const float* pim = (const float*)d_in[1];
    const float* rre = (const float*)d_in[2];
    const float* rim = (const float*)d_in[3];
    float* out = (float*)d_out;

    init_gl_kernel<<<1, 128>>>();
    zero_out_kernel<<<(BATCH * LTAU + 255) / 256, 256>>>(out);
    gtau_kernel<<<512, 256>>>(pre, pim, rre, rim, out);
    g0_kernel<<<BATCH, 256>>>(pre, pim, rre, rim, out);
}

// round 5
// speedup vs baseline: 3.7104x; 1.3465x over previous
#include <cuda_runtime.h>

#define N_GL    256
#define LTAU    1000
#define BATCH   16
#define NPOLES  16
#define NPAIR   8

__device__ float g_phi[N_GL];
__device__ float g_w[N_GL];

// ---- f32x2 packed helpers (sm_103a) ---------------------------------------
__device__ __forceinline__ unsigned long long pk2(float lo, float hi) {
    unsigned long long r;
    asm("mov.b64 %0,{%1,%2};" : "=l"(r) : "f"(lo), "f"(hi));
    return r;
}
__device__ __forceinline__ void upk2(unsigned long long v, float& lo, float& hi) {
    asm("mov.b64 {%0,%1},%2;" : "=f"(lo), "=f"(hi) : "l"(v));
}
__device__ __forceinline__ unsigned long long fma2(unsigned long long a,
                                                   unsigned long long b,
                                                   unsigned long long c) {
    unsigned long long r;
    asm("fma.rn.f32x2 %0,%1,%2,%3;" : "=l"(r) : "l"(a), "l"(b), "l"(c));
    return r;
}
__device__ __forceinline__ unsigned long long mul2(unsigned long long a,
                                                   unsigned long long b) {
    unsigned long long r;
    asm("mul.rn.f32x2 %0,%1,%2;" : "=l"(r) : "l"(a), "l"(b));
    return r;
}

// ---------------------------------------------------------------------------
// Kernel A: block 0 computes Gauss-Legendre nodes/weights (fp32 Newton);
// blocks 1..63 zero the output buffer.
// ---------------------------------------------------------------------------
__global__ void __launch_bounds__(128) initzero_kernel(float* __restrict__ out) {
    const int t = threadIdx.x;
    if (blockIdx.x != 0) {
        int i = (blockIdx.x - 1) * 128 + t;
        for (; i < BATCH * LTAU; i += 63 * 128) out[i] = 0.0f;
        return;
    }

    __shared__ float cA[N_GL + 1], cB[N_GL + 1];
    for (int j = t; j <= N_GL; j += 128) {
        float inv = (j == 0) ? 0.0f : 1.0f / (float)j;
        cA[j] = 2.0f - inv;
        cB[j] = 1.0f - inv;
    }
    __syncthreads();

    const float PI = 3.14159265358979323846f;
    float z = cosf(PI * ((float)t + 0.75f) / ((float)N_GL + 0.5f));

    float pp = 1.0f;
    for (int pass = 0; pass < 3; ++pass) {
        float p1 = 1.0f, p2 = 0.0f;
#pragma unroll 8
        for (int j = 1; j <= N_GL; ++j) {
            float p3 = p2;
            p2 = p1;
            p1 = fmaf(cA[j] * z, p2, -cB[j] * p3);
        }
        pp = (float)N_GL * (z * p1 - p2) / (z * z - 1.0f);
        z -= p1 / pp;
    }

    float wgt = 2.0f / ((1.0f - z * z) * pp * pp);
    float ph  = tanf(0.5f * PI * z);

    g_phi[N_GL - 1 - t] = ph;
    g_phi[t]            = -ph;
    g_w[N_GL - 1 - t]   = wgt;
    g_w[t]              = wgt;
}

// ---------------------------------------------------------------------------
// Kernel B: blocks 0..511 quadrature (geometric recurrence, f32x2 packed,
// early exit); blocks 512..527 Matsubara G0 (writes out[b,0] exclusively;
// gtau blocks skip l==0).
// ---------------------------------------------------------------------------
__global__ void __launch_bounds__(256) main_kernel(
    const float* __restrict__ poles_re,
    const float* __restrict__ poles_im,
    const float* __restrict__ res_re,
    const float* __restrict__ res_im,
    float* __restrict__ out)
{
    const int t    = threadIdx.x;
    const int lane = t & 31;
    const int wid  = t >> 5;

    if (blockIdx.x < 512) {
        // ------------------------- gtau -----------------------------------
        __shared__ float sF[2][8][32];
        __shared__ float sB[2][8][32];
        __shared__ int   sNeed[8];

        const int B    = blockIdx.x;
        const int b    = B >> 5;
        const int node = ((B & 31) << 3) + wid;

        const float phi = g_phi[node];
        const float w   = g_w[node];

        float Ev[NPOLES], CFv[NPOLES], CBv[NPOLES], Mv[NPOLES];
        int myNeed = 1;
#pragma unroll
        for (int p = 0; p < NPOLES; ++p) {
            float eps =  poles_re[b * NPOLES + p];
            float gam = -poles_im[b * NPOLES + p];
            float a   =  res_re[b * NPOLES + p];
            float bb  =  res_im[b * NPOLES + p];

            float om = fmaf(gam, phi, eps);
            float s  = fabsf(om);
            float numer = 0.5f * w * fmaf(-bb, phi, a);
            float C = numer / (1.0f + __expf(-10.0f * s));
            bool fwd = (om >= 0.0f);
            CFv[p] = fwd ? C : 0.0f;
            CBv[p] = fwd ? 0.0f : C;
            Mv[p]  = __expf(-0.32f * s);
            float k = fwd ? (float)lane : (float)(lane + 1);
            Ev[p] = __expf(-0.01f * k * s);
            float ndf = fminf(__fdividef(96.0f, s) + 1.0f, 32.0f);
            int nd = (int)ndf;
            myNeed = max(myNeed, nd);
        }
        if (lane == 0) sNeed[wid] = myNeed;

        unsigned long long E2[NPAIR], CF2[NPAIR], CB2[NPAIR], M2[NPAIR];
#pragma unroll
        for (int q = 0; q < NPAIR; ++q) {
            E2[q]  = pk2(Ev[q],  Ev[q + 8]);
            CF2[q] = pk2(CFv[q], CFv[q + 8]);
            CB2[q] = pk2(CBv[q], CBv[q + 8]);
            M2[q]  = pk2(Mv[q],  Mv[q + 8]);
        }
        __syncthreads();

        int blkNeed = sNeed[0];
#pragma unroll
        for (int q = 1; q < 8; ++q) blkNeed = max(blkNeed, sNeed[q]);

        float* outb = out + b * LTAU;

        for (int c = 0; c < blkNeed; ++c) {
            float aF = 0.0f, aB = 0.0f;
            if (c < myNeed) {
                unsigned long long aF2 = 0ull, aB2 = 0ull;
#pragma unroll
                for (int q = 0; q < NPAIR; ++q) {
                    aF2 = fma2(CF2[q], E2[q], aF2);
                    aB2 = fma2(CB2[q], E2[q], aB2);
                    E2[q] = mul2(E2[q], M2[q]);
                }
                float lo, hi;
                upk2(aF2, lo, hi); aF = lo + hi;
                upk2(aB2, lo, hi); aB = lo + hi;
            }
            const int buf = c & 1;
            sF[buf][wid][lane] = aF;
            sB[buf][wid][lane] = aB;
            __syncthreads();
            if (wid == 0) {
                float v = sF[buf][0][lane] + sF[buf][1][lane] + sF[buf][2][lane]
                        + sF[buf][3][lane] + sF[buf][4][lane] + sF[buf][5][lane]
                        + sF[buf][6][lane] + sF[buf][7][lane];
                int l = c * 32 + lane;
                if (l > 0 && l < LTAU) atomicAdd(outb + l, v);
            } else if (wid == 1) {
                float v = sB[buf][0][lane] + sB[buf][1][lane] + sB[buf][2][lane]
                        + sB[buf][3][lane] + sB[buf][4][lane] + sB[buf][5][lane]
                        + sB[buf][6][lane] + sB[buf][7][lane];
                int l = (LTAU - 1) - (c * 32 + lane);
                if (l > 0) atomicAdd(outb + l, v);
            }
        }
    } else {
        // ------------------------- g0 -------------------------------------
        __shared__ float s_red[8];
        const int b = blockIdx.x - 512;

        float eps[NPOLES], gam[NPOLES], av[NPOLES], bv[NPOLES];
        float SRc1 = 0.0f, SRc2 = 0.0f, SIc3 = 0.0f, SRc4 = 0.0f, SIc5 = 0.0f;
#pragma unroll
        for (int p = 0; p < NPOLES; ++p) {
            float e =  poles_re[b * NPOLES + p];
            float g = -poles_im[b * NPOLES + p];
            float a =  res_re[b * NPOLES + p];
            float bb = res_im[b * NPOLES + p];
            eps[p] = e; gam[p] = g; av[p] = a; bv[p] = bb;
            float cr = -a, ci = -bb;
            float r2 = cr * e + ci * g, i2 = ci * e - cr * g;
            float r3 = r2 * e + i2 * g, i3 = i2 * e - r2 * g;
            float r4 = r3 * e + i3 * g, i4 = i3 * e - r3 * g;
            float i5 = i4 * e - r4 * g;
            SRc1 += cr; SRc2 += r2; SIc3 += i3; SRc4 += r4; SIc5 += i5;
        }

        const double PI = 3.14159265358979323846;
        const float wn = (float)((2.0 * (double)t + 1.0) * (PI / 10.0));

        float reS = 0.0f;
#pragma unroll
        for (int p = 0; p < NPOLES; ++p) {
            float d = gam[p] + wn;
            reS += (av[p] * eps[p] - bv[p] * d) / (eps[p] * eps[p] + d * d);
        }
        float iw  = 1.0f / wn;
        float iw2 = iw * iw;
        float reG = reS + iw2 * (SRc2 + SIc3 * iw - SRc4 * iw2 - SIc5 * iw2 * iw);

        float acc = reG;
#pragma unroll
        for (int off = 16; off > 0; off >>= 1)
            acc += __shfl_xor_sync(0xffffffffu, acc, off);
        if (lane == 0) s_red[wid] = acc;
        __syncthreads();
        if (t < 8) {
            float v = s_red[t];
#pragma unroll
            for (int off = 4; off > 0; off >>= 1)
                v += __shfl_xor_sync(0xffu, v, off);
            if (t == 0) {
                const float C0 = -0.5f;
                const float C1 = -2.5f;
                const float C2 = (float)(-7.0 * 1.2020569031595942 * 100.0 /
                                         (4.0 * PI * PI * PI));
                const float C3 = (float)(1000.0 / 48.0);
                const float C4 = (float)(31.0 * 1.0369277551433699 * 10000.0 /
                                         (16.0 * PI * PI * PI * PI * PI));
                float G0 = C0 * SRc1 + C1 * SRc2 + C2 * SIc3 + C3 * SRc4
                         + C4 * SIc5 + 0.2f * v;
                out[b * LTAU + 0] = G0;
            }
        }
    }
}

extern "C" void kernel_launch(void* const* d_in, const int* in_sizes, int n_in,
                              void* d_out, int out_size) {
    (void)in_sizes; (void)n_in; (void)out_size;
    const float* pre = (const float*)d_in[0];
    const float* pim = (const float*)d_in[1];
    const float* rre = (const float*)d_in[2];
    const float* rim = (const float*)d_in[3];
    float* out = (float*)d_out;

    initzero_kernel<<<64, 128>>>(out);
    main_kernel<<<528, 256>>>(pre, pim, rre, rim, out);
}

// round 8
// speedup vs baseline: 3.7485x; 1.0103x over previous
#include <cuda_runtime.h>

#define N_GL    256
#define LTAU    1000
#define BATCH   16
#define NPOLES  16
#define NPAIR   8

__device__ float g_phi[N_GL];
__device__ float g_w[N_GL];

// ---- f32x2 packed helpers (sm_103a) ---------------------------------------
__device__ __forceinline__ unsigned long long pk2(float lo, float hi) {
    unsigned long long r;
    asm("mov.b64 %0,{%1,%2};" : "=l"(r) : "f"(lo), "f"(hi));
    return r;
}
__device__ __forceinline__ void upk2(unsigned long long v, float& lo, float& hi) {
    asm("mov.b64 {%0,%1},%2;" : "=f"(lo), "=f"(hi) : "l"(v));
}
__device__ __forceinline__ unsigned long long fma2(unsigned long long a,
                                                   unsigned long long b,
                                                   unsigned long long c) {
    unsigned long long r;
    asm("fma.rn.f32x2 %0,%1,%2,%3;" : "=l"(r) : "l"(a), "l"(b), "l"(c));
    return r;
}
__device__ __forceinline__ unsigned long long mul2(unsigned long long a,
                                                   unsigned long long b) {
    unsigned long long r;
    asm("mul.rn.f32x2 %0,%1,%2;" : "=l"(r) : "l"(a), "l"(b));
    return r;
}

// ---------------------------------------------------------------------------
// Kernel A: blocks 0..7 compute Gauss-Legendre nodes/weights via a warp-level
// matrix scan of the Legendre 3-term recurrence (one root per warp, 128 warps
// total -> ~300cyc/pass instead of a 3072cyc serial chain). Blocks 8..9 zero
// the output buffer.
// ---------------------------------------------------------------------------
__global__ void __launch_bounds__(512) initzero_kernel(float* __restrict__ out) {
    const int t = threadIdx.x;

    if (blockIdx.x >= 8) {
        float4* o4 = (float4*)out;
        const float4 z4 = make_float4(0.f, 0.f, 0.f, 0.f);
        for (int i = (blockIdx.x - 8) * 512 + t; i < (BATCH * LTAU) / 4; i += 1024)
            o4[i] = z4;
        return;
    }

    const int lane = t & 31;
    const int wid  = t >> 5;
    const int r    = blockIdx.x * 16 + wid;          // root index 0..127

    const float PI = 3.14159265358979323846f;
    float z = cosf(PI * ((float)r + 0.75f) / 256.5f);

    // recurrence coefs for this lane's j-range: j = 8*lane+1 .. 8*lane+8
    float Aj[8], Bj[8];
#pragma unroll
    for (int k = 0; k < 8; ++k) {
        float j   = (float)(8 * lane + 1 + k);
        float inv = __fdividef(1.0f, j);
        Aj[k] = 2.0f - inv;
        Bj[k] = 1.0f - inv;
    }

    float p1 = 1.0f, p2 = 0.0f, pp = 1.0f;
    for (int pass = 0; pass < 3; ++pass) {
        // local product of 8 step-matrices  M_j = [[A_j z, -B_j],[1,0]]
        float m00 = 1.0f, m01 = 0.0f, m10 = 0.0f, m11 = 1.0f;
#pragma unroll
        for (int k = 0; k < 8; ++k) {
            float a   = Aj[k] * z;
            float n00 = fmaf(a, m00, -Bj[k] * m10);
            float n01 = fmaf(a, m01, -Bj[k] * m11);
            m10 = m00; m11 = m01;
            m00 = n00; m01 = n01;
        }
        // inclusive Kogge-Stone scan (my matrix on the LEFT of lower lanes)
#pragma unroll
        for (int off = 1; off < 32; off <<= 1) {
            float q00 = __shfl_up_sync(0xffffffffu, m00, off);
            float q01 = __shfl_up_sync(0xffffffffu, m01, off);
            float q10 = __shfl_up_sync(0xffffffffu, m10, off);
            float q11 = __shfl_up_sync(0xffffffffu, m11, off);
            if (lane >= off) {
                float n00 = m00 * q00 + m01 * q10;
                float n01 = m00 * q01 + m01 * q11;
                float n10 = m10 * q00 + m11 * q10;
                float n11 = m10 * q01 + m11 * q11;
                m00 = n00; m01 = n01; m10 = n10; m11 = n11;
            }
        }
        // full product applied to v0=[P_0,P_-1]=[1,0]:  P_256 = m00, P_255 = m10
        p1 = __shfl_sync(0xffffffffu, m00, 31);
        p2 = __shfl_sync(0xffffffffu, m10, 31);
        pp = 256.0f * (z * p1 - p2) / (z * z - 1.0f);
        z -= p1 / pp;
    }

    if (lane == 0) {
        float wgt = 2.0f / ((1.0f - z * z) * pp * pp);
        float ph  = tanf(0.5f * PI * z);
        g_phi[N_GL - 1 - r] = ph;
        g_phi[r]            = -ph;
        g_w[N_GL - 1 - r]   = wgt;
        g_w[r]              = wgt;
    }
}

// ---------------------------------------------------------------------------
// Kernel B: blocks 0..511 quadrature -- one node per warp, warps fully
// independent (no smem, no __syncthreads): geometric recurrence over tau,
// f32x2 packed poles, per-warp early exit, direct RED.ADD of each 32-lane
// chunk into the output. Blocks 512..527: Matsubara G0 (owns out[b,0]).
// ---------------------------------------------------------------------------
__global__ void __launch_bounds__(256) main_kernel(
    const float* __restrict__ poles_re,
    const float* __restrict__ poles_im,
    const float* __restrict__ res_re,
    const float* __restrict__ res_im,
    float* __restrict__ out)
{
    const int t    = threadIdx.x;
    const int lane = t & 31;
    const int wid  = t >> 5;

    if (blockIdx.x < 512) {
        // ------------------------- gtau -----------------------------------
        const int B    = blockIdx.x;
        const int b    = B >> 5;
        const int node = ((B & 31) << 3) + wid;

        const float phi = g_phi[node];
        const float w   = g_w[node];

        float Ev[NPOLES], CFv[NPOLES], CBv[NPOLES], Mv[NPOLES];
        int myNeed = 1;                               // warp-uniform
#pragma unroll
        for (int p = 0; p < NPOLES; ++p) {
            float eps =  poles_re[b * NPOLES + p];
            float gam = -poles_im[b * NPOLES + p];
            float a   =  res_re[b * NPOLES + p];
            float bb  =  res_im[b * NPOLES + p];

            float om = fmaf(gam, phi, eps);
            float s  = fabsf(om);
            float numer = 0.5f * w * fmaf(-bb, phi, a);
            float C = numer / (1.0f + __expf(-10.0f * s));
            bool fwd = (om >= 0.0f);
            CFv[p] = fwd ? C : 0.0f;
            CBv[p] = fwd ? 0.0f : C;
            Mv[p]  = __expf(-0.32f * s);
            float k = fwd ? (float)lane : (float)(lane + 1);
            Ev[p] = __expf(-0.01f * k * s);
            float ndf = fminf(__fdividef(96.0f, s) + 1.0f, 32.0f);
            myNeed = max(myNeed, (int)ndf);
        }

        unsigned long long E2[NPAIR], CF2[NPAIR], CB2[NPAIR], M2[NPAIR];
#pragma unroll
        for (int q = 0; q < NPAIR; ++q) {
            E2[q]  = pk2(Ev[q],  Ev[q + 8]);
            CF2[q] = pk2(CFv[q], CFv[q + 8]);
            CB2[q] = pk2(CBv[q], CBv[q + 8]);
            M2[q]  = pk2(Mv[q],  Mv[q + 8]);
        }

        float* outb = out + b * LTAU;

        for (int c = 0; c < myNeed; ++c) {
            unsigned long long aF2 = 0ull, aB2 = 0ull;
#pragma unroll
            for (int q = 0; q < NPAIR; ++q) {
                aF2 = fma2(CF2[q], E2[q], aF2);
                aB2 = fma2(CB2[q], E2[q], aB2);
                E2[q] = mul2(E2[q], M2[q]);
            }
            float f0, f1, b0, b1;
            upk2(aF2, f0, f1);
            upk2(aB2, b0, b1);
            float aF = f0 + f1;
            float aB = b0 + b1;

            int lF = (c << 5) + lane;
            if (aF != 0.0f && lF > 0 && lF < LTAU) atomicAdd(outb + lF, aF);
            int lB = (LTAU - 1) - lF;
            if (aB != 0.0f && lB > 0) atomicAdd(outb + lB, aB);
        }
    } else {
        // ------------------------- g0 -------------------------------------
        __shared__ float s_red[8];
        const int b = blockIdx.x - 512;

        float eps[NPOLES], gam[NPOLES], av[NPOLES], bv[NPOLES];
        float SRc1 = 0.0f, SRc2 = 0.0f, SIc3 = 0.0f, SRc4 = 0.0f, SIc5 = 0.0f;
#pragma unroll
        for (int p = 0; p < NPOLES; ++p) {
            float e =  poles_re[b * NPOLES + p];
            float g = -poles_im[b * NPOLES + p];
            float a =  res_re[b * NPOLES + p];
            float bb = res_im[b * NPOLES + p];
            eps[p] = e; gam[p] = g; av[p] = a; bv[p] = bb;
            float cr = -a, ci = -bb;
            float r2 = cr * e + ci * g, i2 = ci * e - cr * g;
            float r3 = r2 * e + i2 * g, i3 = i2 * e - r2 * g;
            float r4 = r3 * e + i3 * g, i4 = i3 * e - r3 * g;
            float i5 = i4 * e - r4 * g;
            SRc1 += cr; SRc2 += r2; SIc3 += i3; SRc4 += r4; SIc5 += i5;
        }

        const double PI = 3.14159265358979323846;
        const float wn = (float)((2.0 * (double)t + 1.0) * (PI / 10.0));

        float reS = 0.0f;
#pragma unroll
        for (int p = 0; p < NPOLES; ++p) {
            float d = gam[p] + wn;
            reS += (av[p] * eps[p] - bv[p] * d) / (eps[p] * eps[p] + d * d);
        }
        float iw  = 1.0f / wn;
        float iw2 = iw * iw;
        float reG = reS + iw2 * (SRc2 + SIc3 * iw - SRc4 * iw2 - SIc5 * iw2 * iw);

        float acc = reG;
#pragma unroll
        for (int off = 16; off > 0; off >>= 1)
            acc += __shfl_xor_sync(0xffffffffu, acc, off);
        if (lane == 0) s_red[wid] = acc;
        __syncthreads();
        if (t < 8) {
            float v = s_red[t];
#pragma unroll
            for (int off = 4; off > 0; off >>= 1)
                v += __shfl_xor_sync(0xffu, v, off);
            if (t == 0) {
                const float C0 = -0.5f;
                const float C1 = -2.5f;
                const float C2 = (float)(-7.0 * 1.2020569031595942 * 100.0 /
                                         (4.0 * PI * PI * PI));
                const float C3 = (float)(1000.0 / 48.0);
                const float C4 = (float)(31.0 * 1.0369277551433699 * 10000.0 /
                                         (16.0 * PI * PI * PI * PI * PI));
                float G0 = C0 * SRc1 + C1 * SRc2 + C2 * SIc3 + C3 * SRc4
                         + C4 * SIc5 + 0.2f * v;
                out[b * LTAU + 0] = G0;
            }
        }
    }
}

extern "C" void kernel_launch(void* const* d_in, const int* in_sizes, int n_in,
                              void* d_out, int out_size) {
    (void)in_sizes; (void)n_in; (void)out_size;
    const float* pre = (const float*)d_in[0];
    const float* pim = (const float*)d_in[1];
    const float* rre = (const float*)d_in[2];
    const float* rim = (const float*)d_in[3];
    float* out = (float*)d_out;

    initzero_kernel<<<10, 512>>>(out);
    main_kernel<<<528, 256>>>(pre, pim, rre, rim, out);
}

// round 9
// speedup vs baseline: 5.0428x; 1.3453x over previous
#include <cuda_runtime.h>

#define N_GL    256
#define LTAU    1000
#define BATCH   16
#define NPOLES  16
#define NPAIR   8

__device__ float g_phi[N_GL];
__device__ float g_w[N_GL];

// ---- f32x2 packed helpers (sm_103a) ---------------------------------------
__device__ __forceinline__ unsigned long long pk2(float lo, float hi) {
    unsigned long long r;
    asm("mov.b64 %0,{%1,%2};" : "=l"(r) : "f"(lo), "f"(hi));
    return r;
}
__device__ __forceinline__ void upk2(unsigned long long v, float& lo, float& hi) {
    asm("mov.b64 {%0,%1},%2;" : "=f"(lo), "=f"(hi) : "l"(v));
}
__device__ __forceinline__ unsigned long long fma2(unsigned long long a,
                                                   unsigned long long b,
                                                   unsigned long long c) {
    unsigned long long r;
    asm("fma.rn.f32x2 %0,%1,%2,%3;" : "=l"(r) : "l"(a), "l"(b), "l"(c));
    return r;
}
__device__ __forceinline__ unsigned long long mul2(unsigned long long a,
                                                   unsigned long long b) {
    unsigned long long r;
    asm("mul.rn.f32x2 %0,%1,%2;" : "=l"(r) : "l"(a), "l"(b));
    return r;
}

// ---------------------------------------------------------------------------
// Kernel A: blocks 0..7 Gauss-Legendre via warp matrix-scan; blocks 8..9 zero
// the output buffer.
// ---------------------------------------------------------------------------
__global__ void __launch_bounds__(512) initzero_kernel(float* __restrict__ out) {
    const int t = threadIdx.x;

    if (blockIdx.x >= 8) {
        float4* o4 = (float4*)out;
        const float4 z4 = make_float4(0.f, 0.f, 0.f, 0.f);
        for (int i = (blockIdx.x - 8) * 512 + t; i < (BATCH * LTAU) / 4; i += 1024)
            o4[i] = z4;
        return;
    }

    const int lane = t & 31;
    const int wid  = t >> 5;
    const int r    = blockIdx.x * 16 + wid;          // root index 0..127

    const float PI = 3.14159265358979323846f;
    float z = cosf(PI * ((float)r + 0.75f) / 256.5f);

    float Aj[8], Bj[8];
#pragma unroll
    for (int k = 0; k < 8; ++k) {
        float j   = (float)(8 * lane + 1 + k);
        float inv = __fdividef(1.0f, j);
        Aj[k] = 2.0f - inv;
        Bj[k] = 1.0f - inv;
    }

    float p1 = 1.0f, p2 = 0.0f, pp = 1.0f;
    for (int pass = 0; pass < 3; ++pass) {
        float m00 = 1.0f, m01 = 0.0f, m10 = 0.0f, m11 = 1.0f;
#pragma unroll
        for (int k = 0; k < 8; ++k) {
            float a   = Aj[k] * z;
            float n00 = fmaf(a, m00, -Bj[k] * m10);
            float n01 = fmaf(a, m01, -Bj[k] * m11);
            m10 = m00; m11 = m01;
            m00 = n00; m01 = n01;
        }
#pragma unroll
        for (int off = 1; off < 32; off <<= 1) {
            float q00 = __shfl_up_sync(0xffffffffu, m00, off);
            float q01 = __shfl_up_sync(0xffffffffu, m01, off);
            float q10 = __shfl_up_sync(0xffffffffu, m10, off);
            float q11 = __shfl_up_sync(0xffffffffu, m11, off);
            if (lane >= off) {
                float n00 = m00 * q00 + m01 * q10;
                float n01 = m00 * q01 + m01 * q11;
                float n10 = m10 * q00 + m11 * q10;
                float n11 = m10 * q01 + m11 * q11;
                m00 = n00; m01 = n01; m10 = n10; m11 = n11;
            }
        }
        p1 = __shfl_sync(0xffffffffu, m00, 31);
        p2 = __shfl_sync(0xffffffffu, m10, 31);
        pp = 256.0f * (z * p1 - p2) / (z * z - 1.0f);
        z -= p1 / pp;
    }

    if (lane == 0) {
        float wgt = 2.0f / ((1.0f - z * z) * pp * pp);
        float ph  = tanf(0.5f * PI * z);
        g_phi[N_GL - 1 - r] = ph;
        g_phi[r]            = -ph;
        g_w[N_GL - 1 - r]   = wgt;
        g_w[r]              = wgt;
    }
}

// ---------------------------------------------------------------------------
// Kernel B: blocks 0..511 quadrature. Each warp owns one node and a PRIVATE
// 8KB smem slab (1024 fwd + 1024 bwd floats). The chunk loop writes plain STS
// (no atomics, no guards: raw index 32c+lane is always in [0,1023]; bwd slab
// is in raw-index space, l = 999-idx). One __syncthreads, then each warp sums
// the block's 16 slabs over its 128-l slice and issues 4 global REDs.
// Blocks 512..527: Matsubara G0 (owns out[b,0]; gtau adds exactly 0 there).
// ---------------------------------------------------------------------------
__global__ void __launch_bounds__(256) main_kernel(
    const float* __restrict__ poles_re,
    const float* __restrict__ poles_im,
    const float* __restrict__ res_re,
    const float* __restrict__ res_im,
    float* __restrict__ out)
{
    extern __shared__ float slab[];   // [8 warps][2048]  (F: 0..1023, B: 1024..2047)

    const int t    = threadIdx.x;
    const int lane = t & 31;
    const int wid  = t >> 5;

    if (blockIdx.x < 512) {
        // ------------------------- gtau -----------------------------------
        const int B    = blockIdx.x;
        const int b    = B >> 5;
        const int node = ((B & 31) << 3) + wid;

        float* myF = slab + wid * 2048;
        float* myB = myF + 1024;

        // zero own slab (512 float4 / 32 lanes = 16 per lane)
        {
            float4* s4 = (float4*)myF;
            const float4 z4 = make_float4(0.f, 0.f, 0.f, 0.f);
#pragma unroll
            for (int i = 0; i < 16; ++i) s4[i * 32 + lane] = z4;
        }

        const float phi = g_phi[node];
        const float w   = g_w[node];

        float Ev[NPOLES], CFv[NPOLES], CBv[NPOLES], Mv[NPOLES];
        int myNeed = 1;                               // warp-uniform
#pragma unroll
        for (int p = 0; p < NPOLES; ++p) {
            float eps =  poles_re[b * NPOLES + p];
            float gam = -poles_im[b * NPOLES + p];
            float a   =  res_re[b * NPOLES + p];
            float bb  =  res_im[b * NPOLES + p];

            float om = fmaf(gam, phi, eps);
            float s  = fabsf(om);
            float numer = 0.5f * w * fmaf(-bb, phi, a);
            float C = numer / (1.0f + __expf(-10.0f * s));
            bool fwd = (om >= 0.0f);
            CFv[p] = fwd ? C : 0.0f;
            CBv[p] = fwd ? 0.0f : C;
            Mv[p]  = __expf(-0.32f * s);
            float k = fwd ? (float)lane : (float)(lane + 1);
            Ev[p] = __expf(-0.01f * k * s);
            float ndf = fminf(__fdividef(64.0f, s) + 1.0f, 32.0f);
            myNeed = max(myNeed, (int)ndf);
        }

        unsigned long long E2[NPAIR], CF2[NPAIR], CB2[NPAIR], M2[NPAIR];
#pragma unroll
        for (int q = 0; q < NPAIR; ++q) {
            E2[q]  = pk2(Ev[q],  Ev[q + 8]);
            CF2[q] = pk2(CFv[q], CFv[q + 8]);
            CB2[q] = pk2(CBv[q], CBv[q + 8]);
            M2[q]  = pk2(Mv[q],  Mv[q + 8]);
        }

        for (int c = 0; c < myNeed; ++c) {
            unsigned long long aF2 = 0ull, aB2 = 0ull;
#pragma unroll
            for (int q = 0; q < NPAIR; ++q) {
                aF2 = fma2(CF2[q], E2[q], aF2);
                aB2 = fma2(CB2[q], E2[q], aB2);
                E2[q] = mul2(E2[q], M2[q]);
            }
            float f0, f1, b0, b1;
            upk2(aF2, f0, f1);
            upk2(aB2, b0, b1);
            int idx = (c << 5) + lane;
            myF[idx] = f0 + f1;
            myB[idx] = b0 + b1;
        }

        __syncthreads();

        // epilogue: warp wid sums 16 slabs over l in [128*wid, 128*wid+127]
        const int l = (wid << 7) + (lane << 2);
        if (l < LTAU) {
            float ax = 0.f, ay = 0.f, az = 0.f, aw = 0.f;
#pragma unroll
            for (int w2 = 0; w2 < 8; ++w2) {
                const float* base = slab + w2 * 2048;
                float4 f  = *(const float4*)(base + l);
                float4 bq = *(const float4*)(base + 1024 + (996 - l));
                // bq components map to l+3, l+2, l+1, l
                ax += f.x + bq.w;
                ay += f.y + bq.z;
                az += f.z + bq.y;
                aw += f.w + bq.x;
            }
            if (l == 0) ax = 0.0f;        // l==0 belongs to g0; add exact 0
            float* o = out + b * LTAU + l;
            atomicAdd(o + 0, ax);
            atomicAdd(o + 1, ay);
            atomicAdd(o + 2, az);
            atomicAdd(o + 3, aw);
        }
    } else {
        // ------------------------- g0 -------------------------------------
        __shared__ float s_red[8];
        const int b = blockIdx.x - 512;

        float eps[NPOLES], gam[NPOLES], av[NPOLES], bv[NPOLES];
        float SRc1 = 0.0f, SRc2 = 0.0f, SIc3 = 0.0f, SRc4 = 0.0f, SIc5 = 0.0f;
#pragma unroll
        for (int p = 0; p < NPOLES; ++p) {
            float e =  poles_re[b * NPOLES + p];
            float g = -poles_im[b * NPOLES + p];
            float a =  res_re[b * NPOLES + p];
            float bb = res_im[b * NPOLES + p];
            eps[p] = e; gam[p] = g; av[p] = a; bv[p] = bb;
            float cr = -a, ci = -bb;
            float r2 = cr * e + ci * g, i2 = ci * e - cr * g;
            float r3 = r2 * e + i2 * g, i3 = i2 * e - r2 * g;
            float r4 = r3 * e + i3 * g, i4 = i3 * e - r3 * g;
            float i5 = i4 * e - r4 * g;
            SRc1 += cr; SRc2 += r2; SIc3 += i3; SRc4 += r4; SIc5 += i5;
        }

        const double PI = 3.14159265358979323846;
        const float wn = (float)((2.0 * (double)t + 1.0) * (PI / 10.0));

        float reS = 0.0f;
#pragma unroll
        for (int p = 0; p < NPOLES; ++p) {
            float d = gam[p] + wn;
            reS += (av[p] * eps[p] - bv[p] * d) / (eps[p] * eps[p] + d * d);
        }
        float iw  = 1.0f / wn;
        float iw2 = iw * iw;
        float reG = reS + iw2 * (SRc2 + SIc3 * iw - SRc4 * iw2 - SIc5 * iw2 * iw);

        float acc = reG;
#pragma unroll
        for (int off = 16; off > 0; off >>= 1)
            acc += __shfl_xor_sync(0xffffffffu, acc, off);
        if (lane == 0) s_red[wid] = acc;
        __syncthreads();
        if (t < 8) {
            float v = s_red[t];
#pragma unroll
            for (int off = 4; off > 0; off >>= 1)
                v += __shfl_xor_sync(0xffu, v, off);
            if (t == 0) {
                const float C0 = -0.5f;
                const float C1 = -2.5f;
                const float C2 = (float)(-7.0 * 1.2020569031595942 * 100.0 /
                                         (4.0 * PI * PI * PI));
                const float C3 = (float)(1000.0 / 48.0);
                const float C4 = (float)(31.0 * 1.0369277551433699 * 10000.0 /
                                         (16.0 * PI * PI * PI * PI * PI));
                float G0 = C0 * SRc1 + C1 * SRc2 + C2 * SIc3 + C3 * SRc4
                         + C4 * SIc5 + 0.2f * v;
                out[b * LTAU + 0] = G0;
            }
        }
    }
}

extern "C" void kernel_launch(void* const* d_in, const int* in_sizes, int n_in,
                              void* d_out, int out_size) {
    (void)in_sizes; (void)n_in; (void)out_size;
    const float* pre = (const float*)d_in[0];
    const float* pim = (const float*)d_in[1];
    const float* rre = (const float*)d_in[2];
    const float* rim = (const float*)d_in[3];
    float* out = (float*)d_out;

    static int attr_set = 0;
    if (!attr_set) {
        cudaFuncSetAttribute(main_kernel,
                             cudaFuncAttributeMaxDynamicSharedMemorySize,
                             8 * 2048 * (int)sizeof(float));
        attr_set = 1;
    }

    initzero_kernel<<<10, 512>>>(out);
    main_kernel<<<528, 256, 8 * 2048 * sizeof(float)>>>(pre, pim, rre, rim, out);
}

// round 12
// speedup vs baseline: 5.5740x; 1.1053x over previous
#include <cuda_runtime.h>

#define N_GL    256
#define LTAU    1000
#define BATCH   16
#define NPOLES  16
#define NPAIR   8

__device__ float g_phi[N_GL];
__device__ float g_w[N_GL];

// ---- f32x2 packed helpers (sm_103a) ---------------------------------------
__device__ __forceinline__ unsigned long long pk2(float lo, float hi) {
    unsigned long long r;
    asm("mov.b64 %0,{%1,%2};" : "=l"(r) : "f"(lo), "f"(hi));
    return r;
}
__device__ __forceinline__ void upk2(unsigned long long v, float& lo, float& hi) {
    asm("mov.b64 {%0,%1},%2;" : "=f"(lo), "=f"(hi) : "l"(v));
}
__device__ __forceinline__ unsigned long long fma2(unsigned long long a,
                                                   unsigned long long b,
                                                   unsigned long long c) {
    unsigned long long r;
    asm("fma.rn.f32x2 %0,%1,%2,%3;" : "=l"(r) : "l"(a), "l"(b), "l"(c));
    return r;
}
__device__ __forceinline__ unsigned long long mul2(unsigned long long a,
                                                   unsigned long long b) {
    unsigned long long r;
    asm("mul.rn.f32x2 %0,%1,%2;" : "=l"(r) : "l"(a), "l"(b));
    return r;
}
__device__ __forceinline__ unsigned long long add2(unsigned long long a,
                                                   unsigned long long b) {
    unsigned long long r;
    asm("add.rn.f32x2 %0,%1,%2;" : "=l"(r) : "l"(a), "l"(b));
    return r;
}

// ---------------------------------------------------------------------------
// Kernel A: blocks 0..7 Gauss-Legendre via warp matrix-scan; blocks 8..9 zero
// the output buffer.
// ---------------------------------------------------------------------------
__global__ void __launch_bounds__(512) initzero_kernel(float* __restrict__ out) {
    const int t = threadIdx.x;

    if (blockIdx.x >= 8) {
        float4* o4 = (float4*)out;
        const float4 z4 = make_float4(0.f, 0.f, 0.f, 0.f);
        for (int i = (blockIdx.x - 8) * 512 + t; i < (BATCH * LTAU) / 4; i += 1024)
            o4[i] = z4;
        return;
    }

    const int lane = t & 31;
    const int wid  = t >> 5;
    const int r    = blockIdx.x * 16 + wid;          // root index 0..127

    const float PI = 3.14159265358979323846f;
    float z = cosf(PI * ((float)r + 0.75f) / 256.5f);

    float Aj[8], Bj[8];
#pragma unroll
    for (int k = 0; k < 8; ++k) {
        float j   = (float)(8 * lane + 1 + k);
        float inv = __fdividef(1.0f, j);
        Aj[k] = 2.0f - inv;
        Bj[k] = 1.0f - inv;
    }

    float p1 = 1.0f, p2 = 0.0f, pp = 1.0f;
    for (int pass = 0; pass < 3; ++pass) {
        float m00 = 1.0f, m01 = 0.0f, m10 = 0.0f, m11 = 1.0f;
#pragma unroll
        for (int k = 0; k < 8; ++k) {
            float a   = Aj[k] * z;
            float n00 = fmaf(a, m00, -Bj[k] * m10);
            float n01 = fmaf(a, m01, -Bj[k] * m11);
            m10 = m00; m11 = m01;
            m00 = n00; m01 = n01;
        }
#pragma unroll
        for (int off = 1; off < 32; off <<= 1) {
            float q00 = __shfl_up_sync(0xffffffffu, m00, off);
            float q01 = __shfl_up_sync(0xffffffffu, m01, off);
            float q10 = __shfl_up_sync(0xffffffffu, m10, off);
            float q11 = __shfl_up_sync(0xffffffffu, m11, off);
            if (lane >= off) {
                float n00 = m00 * q00 + m01 * q10;
                float n01 = m00 * q01 + m01 * q11;
                float n10 = m10 * q00 + m11 * q10;
                float n11 = m10 * q01 + m11 * q11;
                m00 = n00; m01 = n01; m10 = n10; m11 = n11;
            }
        }
        p1 = __shfl_sync(0xffffffffu, m00, 31);
        p2 = __shfl_sync(0xffffffffu, m10, 31);
        pp = 256.0f * (z * p1 - p2) / (z * z - 1.0f);
        z -= p1 / pp;
    }

    if (lane == 0) {
        float wgt = 2.0f / ((1.0f - z * z) * pp * pp);
        float ph  = tanf(0.5f * PI * z);
        g_phi[N_GL - 1 - r] = ph;
        g_phi[r]            = -ph;
        g_w[N_GL - 1 - r]   = wgt;
        g_w[r]              = wgt;
    }
}

// ---------------------------------------------------------------------------
// Kernel B: blocks 0..511 quadrature. Warp = one node, private 8KB smem slab.
// Loop-carried state per pole-pair: Et (=C*E, advances by M), M, R (+-1 sign).
// Per chunk: T = sum(Et), S = sum(R*Et); fwd slab gets T+S, bwd gets T-S
// (C pre-scaled by 0.25 to absorb the 1/2). Per-warp early exit from s_min
// with exponent cutoff 30. Blocks 512..527: Matsubara G0 (owns out[b,0]).
// ---------------------------------------------------------------------------
__global__ void __launch_bounds__(256, 3) main_kernel(
    const float* __restrict__ poles_re,
    const float* __restrict__ poles_im,
    const float* __restrict__ res_re,
    const float* __restrict__ res_im,
    float* __restrict__ out)
{
    extern __shared__ float slab[];   // [8 warps][2048]  (F: 0..1023, B: 1024..2047)

    const int t    = threadIdx.x;
    const int lane = t & 31;
    const int wid  = t >> 5;

    if (blockIdx.x < 512) {
        // ------------------------- gtau -----------------------------------
        const int B    = blockIdx.x;
        const int b    = B >> 5;
        const int node = ((B & 31) << 3) + wid;

        float* myF = slab + wid * 2048;
        float* myB = myF + 1024;

        // zero own slab (512 float4 / 32 lanes = 16 per lane)
        {
            float4* s4 = (float4*)myF;
            const float4 z4 = make_float4(0.f, 0.f, 0.f, 0.f);
#pragma unroll
            for (int i = 0; i < 16; ++i) s4[i * 32 + lane] = z4;
        }

        const float phi = g_phi[node];
        const float w   = g_w[node];

        float Etv[NPOLES], Mv[NPOLES], Rv[NPOLES];
        float s_min = 1e30f;
#pragma unroll
        for (int p = 0; p < NPOLES; ++p) {
            float eps =  poles_re[b * NPOLES + p];
            float gam = -poles_im[b * NPOLES + p];
            float a   =  res_re[b * NPOLES + p];
            float bb  =  res_im[b * NPOLES + p];

            float om = fmaf(gam, phi, eps);
            float s  = fabsf(om);
            s_min = fminf(s_min, s);
            float numer = 0.25f * w * fmaf(-bb, phi, a);   // extra 0.5 for T+-S fold
            float C = numer / (1.0f + __expf(-10.0f * s));
            bool fwd = (om >= 0.0f);
            Rv[p] = fwd ? 1.0f : -1.0f;
            Mv[p] = __expf(-0.32f * s);
            float k = fwd ? (float)lane : (float)(lane + 1);
            Etv[p] = C * __expf(-0.01f * k * s);
        }
        // chunk c dead when 0.32*c*s_min > 30  ->  c > 93.75/s_min
        int myNeed = min(32, (int)(__fdividef(93.75f, s_min)) + 1);

        unsigned long long Et2[NPAIR], M2[NPAIR], R2[NPAIR];
#pragma unroll
        for (int q = 0; q < NPAIR; ++q) {
            Et2[q] = pk2(Etv[q], Etv[q + 8]);
            M2[q]  = pk2(Mv[q],  Mv[q + 8]);
            R2[q]  = pk2(Rv[q],  Rv[q + 8]);
        }

#pragma unroll 2
        for (int c = 0; c < myNeed; ++c) {
            unsigned long long aT2 = 0ull, aS2 = 0ull;
#pragma unroll
            for (int q = 0; q < NPAIR; ++q) {
                aT2 = add2(aT2, Et2[q]);
                aS2 = fma2(R2[q], Et2[q], aS2);
                Et2[q] = mul2(Et2[q], M2[q]);
            }
            float t0, t1, s0, s1;
            upk2(aT2, t0, t1);
            upk2(aS2, s0, s1);
            float tt = t0 + t1;
            float ss = s0 + s1;
            int idx = (c << 5) + lane;
            myF[idx] = tt + ss;
            myB[idx] = tt - ss;
        }

        __syncthreads();

        // epilogue: warp wid sums 16 slabs over l in [128*wid, 128*wid+127]
        const int l = (wid << 7) + (lane << 2);
        if (l < LTAU) {
            float ax = 0.f, ay = 0.f, az = 0.f, aw = 0.f;
#pragma unroll
            for (int w2 = 0; w2 < 8; ++w2) {
                const float* base = slab + w2 * 2048;
                float4 f  = *(const float4*)(base + l);
                float4 bq = *(const float4*)(base + 1024 + (996 - l));
                // bq components map to l+3, l+2, l+1, l
                ax += f.x + bq.w;
                ay += f.y + bq.z;
                az += f.z + bq.y;
                aw += f.w + bq.x;
            }
            if (l == 0) ax = 0.0f;        // l==0 belongs to g0; add exact 0
            float* o = out + b * LTAU + l;
            atomicAdd(o + 0, ax);
            atomicAdd(o + 1, ay);
            atomicAdd(o + 2, az);
            atomicAdd(o + 3, aw);
        }
    } else {
        // ------------------------- g0 -------------------------------------
        __shared__ float s_red[8];
        const int b = blockIdx.x - 512;

        float eps[NPOLES], gam[NPOLES], av[NPOLES], bv[NPOLES];
        float SRc1 = 0.0f, SRc2 = 0.0f, SIc3 = 0.0f, SRc4 = 0.0f, SIc5 = 0.0f;
#pragma unroll
        for (int p = 0; p < NPOLES; ++p) {
            float e =  poles_re[b * NPOLES + p];
            float g = -poles_im[b * NPOLES + p];
            float a =  res_re[b * NPOLES + p];
            float bb = res_im[b * NPOLES + p];
            eps[p] = e; gam[p] = g; av[p] = a; bv[p] = bb;
            float cr = -a, ci = -bb;
            float r2 = cr * e + ci * g, i2 = ci * e - cr * g;
            float r3 = r2 * e + i2 * g, i3 = i2 * e - r2 * g;
            float r4 = r3 * e + i3 * g, i4 = i3 * e - r3 * g;
            float i5 = i4 * e - r4 * g;
            SRc1 += cr; SRc2 += r2; SIc3 += i3; SRc4 += r4; SIc5 += i5;
        }

        const double PI = 3.14159265358979323846;
        const float wn = (float)((2.0 * (double)t + 1.0) * (PI / 10.0));

        float reS = 0.0f;
#pragma unroll
        for (int p = 0; p < NPOLES; ++p) {
            float d = gam[p] + wn;
            reS += (av[p] * eps[p] - bv[p] * d) / (eps[p] * eps[p] + d * d);
        }
        float iw  = 1.0f / wn;
        float iw2 = iw * iw;
        float reG = reS + iw2 * (SRc2 + SIc3 * iw - SRc4 * iw2 - SIc5 * iw2 * iw);

        float acc = reG;
#pragma unroll
        for (int off = 16; off > 0; off >>= 1)
            acc += __shfl_xor_sync(0xffffffffu, acc, off);
        if (lane == 0) s_red[wid] = acc;
        __syncthreads();
        if (t < 8) {
            float v = s_red[t];
#pragma unroll
            for (int off = 4; off > 0; off >>= 1)
                v += __shfl_xor_sync(0xffu, v, off);
            if (t == 0) {
                const float C0 = -0.5f;
                const float C1 = -2.5f;
                const float C2 = (float)(-7.0 * 1.2020569031595942 * 100.0 /
                                         (4.0 * PI * PI * PI));
                const float C3 = (float)(1000.0 / 48.0);
                const float C4 = (float)(31.0 * 1.0369277551433699 * 10000.0 /
                                         (16.0 * PI * PI * PI * PI * PI));
                float G0 = C0 * SRc1 + C1 * SRc2 + C2 * SIc3 + C3 * SRc4
                         + C4 * SIc5 + 0.2f * v;
                out[b * LTAU + 0] = G0;
            }
        }
    }
}

extern "C" void kernel_launch(void* const* d_in, const int* in_sizes, int n_in,
                              void* d_out, int out_size) {
    (void)in_sizes; (void)n_in; (void)out_size;
    const float* pre = (const float*)d_in[0];
    const float* pim = (const float*)d_in[1];
    const float* rre = (const float*)d_in[2];
    const float* rim = (const float*)d_in[3];
    float* out = (float*)d_out;

    static int attr_set = 0;
    if (!attr_set) {
        cudaFuncSetAttribute(main_kernel,
                             cudaFuncAttributeMaxDynamicSharedMemorySize,
                             8 * 2048 * (int)sizeof(float));
        attr_set = 1;
    }

    initzero_kernel<<<10, 512>>>(out);
    main_kernel<<<528, 256, 8 * 2048 * sizeof(float)>>>(pre, pim, rre, rim, out);
}